// round 7
// baseline (speedup 1.0000x reference)
#include <cuda_runtime.h>
#include <mma.h>
#include <math.h>

#define Bn 8
#define Cc 512
#define HW 4096
#define Mm 1024
#define Dd 64
#define Gg 128

typedef unsigned long long ull;
using namespace nvcuda;

// ---------------- packed f32x2 primitives (Blackwell) ----------------------
__device__ __forceinline__ ull pk2(float lo, float hi) {
    ull r;
    asm("mov.b64 %0, {%1, %2};" : "=l"(r) : "f"(lo), "f"(hi));
    return r;
}
__device__ __forceinline__ ull bc2(float v) { return pk2(v, v); }
__device__ __forceinline__ ull fma2(ull a, ull b, ull c) {
    ull d;
    asm("fma.rn.f32x2 %0, %1, %2, %3;" : "=l"(d) : "l"(a), "l"(b), "l"(c));
    return d;
}
__device__ __forceinline__ ull mul2(ull a, ull b) {
    ull d;
    asm("mul.rn.f32x2 %0, %1, %2;" : "=l"(d) : "l"(a), "l"(b));
    return d;
}
__device__ __forceinline__ void upk2(float& lo, float& hi, ull v) {
    asm("mov.b64 {%0, %1}, %2;" : "=f"(lo), "=f"(hi) : "l"(v));
}
__device__ __forceinline__ float tf32r(float x) {
    float r;
    asm("cvt.rna.tf32.f32 %0, %1;" : "=f"(r) : "f"(x));
    return r;
}

// ---------------- scratch ---------------------------------------------------
__device__ float d_tpg[Bn * 256 * HW];
__device__ float d_phiP[Bn * Dd * Mm];
__device__ float d_gPT[Bn * Mm * Gg];    // pooled g, transposed [b][m][g]
__device__ float d_yT[Bn * Gg * HW];
__device__ float d_S[Gg * Gg];
__device__ float d_mu[Gg];
__device__ float d_meanC[Cc];
__device__ float d_rstdC[Cc];

// ---------------- fast exp on the FMA pipe ----------------------------------
__device__ __forceinline__ float fast_exp(float x) {
    x = fmaxf(x, -87.0f);
    float t = fmaf(x, 1.4426950408889634f, 12582912.0f);
    float n = t - 12582912.0f;
    int e = __float_as_int(t) - 0x4B400000;
    float r = fmaf(n, -6.93145752e-1f, x);
    r = fmaf(n, -1.42860677e-6f, r);
    float p = 1.3888889e-3f;
    p = fmaf(p, r, 8.3333333e-3f);
    p = fmaf(p, r, 4.1666668e-2f);
    p = fmaf(p, r, 1.6666667e-1f);
    p = fmaf(p, r, 5.0e-1f);
    p = fmaf(p, r, 1.0f);
    p = fmaf(p, r, 1.0f);
    return __int_as_float(__float_as_int(p) + (e << 23));
}

// ---------------- kernel 0: zero S, mu --------------------------------------
__global__ void zero_kernel() {
    int i = blockIdx.x * 256 + threadIdx.x;
    if (i < Gg * Gg) d_S[i] = 0.0f;
    if (i < Gg) d_mu[i] = 0.0f;
}

// ======================= WMMA tf32-split GEMM machinery =====================
// smem buffer layout (floats): AH[128*20] | AL[128*20] | BH[16*132] | BL[16*132]
#define WBUF 9344                     // floats per buffer
#define WSMEM_FLOATS (2 * WBUF)       // 18688 floats = 74752 B (epilogue reuses)
typedef wmma::fragment<wmma::matrix_a, 16, 16, 8, wmma::precision::tf32, wmma::row_major> FragA;
typedef wmma::fragment<wmma::matrix_b, 16, 16, 8, wmma::precision::tf32, wmma::row_major> FragB;
typedef wmma::fragment<wmma::accumulator, 16, 16, 8, float> FragC;

__device__ __forceinline__ void w_split_store(float* hdst, float* ldst, float4 v) {
    float4 h, l;
    h.x = tf32r(v.x); l.x = tf32r(v.x - h.x);
    h.y = tf32r(v.y); l.y = tf32r(v.y - h.y);
    h.z = tf32r(v.z); l.z = tf32r(v.z - h.z);
    h.w = tf32r(v.w); l.w = tf32r(v.w - h.w);
    *(float4*)hdst = h;
    *(float4*)ldst = l;
}

// stage A rows from gemm1 weights (th|ph|g concatenated) + B from x
__device__ __forceinline__ void g1_stage(
    float* sm, int buf, int k0, int row0g, int n0, int tid, const float* xb,
    const float* th_w, const float* ph_w, const float* g_w)
{
    float* base = sm + buf * WBUF;
#pragma unroll
    for (int it = 0; it < 2; it++) {
        int f = tid + it * 256;
        int m = f >> 2, kq = (f & 3) * 4;
        int o = row0g + m;
        const float* wr = (o < 64) ? th_w + (size_t)o * Cc
                        : (o < 128) ? ph_w + (size_t)(o - 64) * Cc
                        : g_w + (size_t)(o - 128) * Cc;
        float4 v = *(const float4*)(wr + k0 + kq);
        w_split_store(base + m * 20 + kq, base + 2560 + m * 20 + kq, v);
    }
#pragma unroll
    for (int it = 0; it < 2; it++) {
        int f = tid + it * 256;
        int kk = f >> 5, nq = (f & 31) * 4;
        float4 v = *(const float4*)(xb + (size_t)(k0 + kk) * HW + n0 + nq);
        w_split_store(base + 5120 + kk * 132 + nq, base + 7232 + kk * 132 + nq, v);
    }
}

__device__ __forceinline__ void w_mma_chunk(
    float* base, int mbase, int nbase, FragC acc[4][2])
{
#pragma unroll
    for (int ks = 0; ks < 16; ks += 8) {
        FragB bh[2], bl[2];
#pragma unroll
        for (int j = 0; j < 2; j++) {
            wmma::load_matrix_sync(bh[j], base + 5120 + ks * 132 + nbase + j * 16, 132);
            wmma::load_matrix_sync(bl[j], base + 7232 + ks * 132 + nbase + j * 16, 132);
        }
#pragma unroll
        for (int i = 0; i < 4; i++) {
            FragA ah, al;
            wmma::load_matrix_sync(ah, base + (mbase + i * 16) * 20 + ks, 20);
            wmma::load_matrix_sync(al, base + 2560 + (mbase + i * 16) * 20 + ks, 20);
#pragma unroll
            for (int j = 0; j < 2; j++) {
                wmma::mma_sync(acc[i][j], ah, bh[j], acc[i][j]);
                wmma::mma_sync(acc[i][j], ah, bl[j], acc[i][j]);
                wmma::mma_sync(acc[i][j], al, bh[j], acc[i][j]);
            }
        }
    }
}

// ---------------- kernel 1: conv1x1 (theta|phi|g) via wmma tf32-split -------
__global__ __launch_bounds__(256, 2) void gemm1_wmma_kernel(
    const float* __restrict__ x,
    const float* __restrict__ g_w, const float* __restrict__ g_b,
    const float* __restrict__ th_w, const float* __restrict__ th_b,
    const float* __restrict__ ph_w, const float* __restrict__ ph_b)
{
    extern __shared__ float sm[];
    const int tid = threadIdx.x;
    const int w = tid >> 5;
    const int mbase = (w & 1) * 64;
    const int nbase = (w >> 1) * 32;
    const int b = blockIdx.z;
    const int row0g = blockIdx.y * 128;
    const int n0 = blockIdx.x * 128;
    const float* xb = x + (size_t)b * Cc * HW;

    FragC acc[4][2];
#pragma unroll
    for (int i = 0; i < 4; i++)
#pragma unroll
        for (int j = 0; j < 2; j++) wmma::fill_fragment(acc[i][j], 0.0f);

    g1_stage(sm, 0, 0, row0g, n0, tid, xb, th_w, ph_w, g_w);
    for (int c = 0; c < Cc / 16; c++) {
        __syncthreads();
        if (c + 1 < Cc / 16)
            g1_stage(sm, (c + 1) & 1, (c + 1) * 16, row0g, n0, tid, xb, th_w, ph_w, g_w);
        w_mma_chunk(sm + (c & 1) * WBUF, mbase, nbase, acc);
    }

    __syncthreads();   // all MMA reads done; reuse smem for epilogue staging
    float* st = sm;    // [128][132]
#pragma unroll
    for (int i = 0; i < 4; i++)
#pragma unroll
        for (int j = 0; j < 2; j++)
            wmma::store_matrix_sync(st + (mbase + i * 16) * 132 + nbase + j * 16,
                                    acc[i][j], 132, wmma::mem_row_major);
    __syncthreads();

#pragma unroll
    for (int it = 0; it < 16; it++) {
        int f = tid + it * 256;
        int row = f >> 5, nq = (f & 31) * 4;
        int o = row0g + row;
        float bv = (o < 64) ? th_b[o] : (o < 128) ? ph_b[o - 64] : g_b[o - 128];
        float4 v = *(float4*)&st[row * 132 + nq];
        v.x += bv; v.y += bv; v.z += bv; v.w += bv;
        *(float4*)(d_tpg + ((size_t)b * 256 + o) * HW + n0 + nq) = v;
    }
}

// ---------------- kernel 2: 2x2 maxpool of phi/g rows -----------------------
__global__ void pool_kernel() {
    int idx = blockIdx.x * 256 + threadIdx.x;
    if (idx >= Bn * 192 * Mm) return;
    int pm = idx & (Mm - 1);
    int c = (idx >> 10) % 192;
    int b = idx / (192 * Mm);
    int ph = pm >> 5, pw = pm & 31;
    const float* src = d_tpg + ((size_t)b * 256 + 64 + c) * HW + (size_t)(ph * 2) * 64 + pw * 2;
    float v = fmaxf(fmaxf(src[0], src[1]), fmaxf(src[64], src[65]));
    if (c < 64) d_phiP[((size_t)b * Dd + c) * Mm + pm] = v;
    else d_gPT[((size_t)b * Mm + pm) * Gg + (c - 64)] = v;
}

// ---------------- kernel 3: fused attention, FFMA2, 2 CTAs/SM ---------------
#define ATT_SMEM_FLOATS (8192 + 8448 + 8192 + 128 + 128)
__global__ __launch_bounds__(256, 2) void attn_kernel() {
    extern __shared__ float smf[];
    float* th_s = smf;                    // [c][n] stride 128
    float* phi_s = smf + 8192;            // [c][m] stride 64 (aliases P)
    float* P_s = smf + 8192;              // [m][n] stride 132
    float* G_s = smf + 16640;             // [m][g] stride 128
    float* scale_s = smf + 24832;         // [128]
    float* l_s = smf + 24960;             // [128]

    const int b = blockIdx.y;
    const int n0 = blockIdx.x * 128;
    const int tid = threadIdx.x;
    const int tx = tid & 15, ty = tid >> 4;
    const int ty8 = ty * 8, tx4 = tx * 4, tx8 = tx * 8;

    const float* thg = d_tpg + (size_t)b * 256 * HW + n0;
    for (int f = tid; f < 64 * 32; f += 256) {
        int c = f >> 5, nq = (f & 31) * 4;
        *(float4*)&th_s[c * 128 + nq] = *(const float4*)(thg + (size_t)c * HW + nq);
    }
    if (tid < 128) l_s[tid] = 0.0f;

    float rm[8];
    ull accp[4][8];
#pragma unroll
    for (int i = 0; i < 8; i++) rm[i] = -1e30f;
#pragma unroll
    for (int r = 0; r < 4; r++)
#pragma unroll
        for (int u = 0; u < 8; u++) accp[r][u] = 0ULL;

    const float* phig = d_phiP + (size_t)b * Dd * Mm;
    const float* gTg = d_gPT + (size_t)b * Mm * Gg;

    for (int m0 = 0; m0 < Mm; m0 += 64) {
        __syncthreads();
        for (int f = tid; f < 64 * 16; f += 256) {
            int c = f >> 4, mq = (f & 15) * 4;
            *(float4*)&phi_s[c * 64 + mq] = *(const float4*)(phig + (size_t)c * Mm + m0 + mq);
        }
        for (int f = tid; f < 64 * 32; f += 256) {
            int m = f >> 5, gq = (f & 31) * 4;
            *(float4*)&G_s[m * 128 + gq] = *(const float4*)(gTg + (size_t)(m0 + m) * Gg + gq);
        }
        __syncthreads();

        ull sp[4][4];
#pragma unroll
        for (int i = 0; i < 4; i++)
#pragma unroll
            for (int j = 0; j < 4; j++) sp[i][j] = 0ULL;
#pragma unroll 8
        for (int c = 0; c < 64; c++) {
            ulonglong2 t0 = *(ulonglong2*)&th_s[c * 128 + ty8];
            ulonglong2 t1 = *(ulonglong2*)&th_s[c * 128 + ty8 + 4];
            ull ap[4] = {t0.x, t0.y, t1.x, t1.y};
            float4 bb = *(float4*)&phi_s[c * 64 + tx4];
            ull bp[4] = {bc2(bb.x), bc2(bb.y), bc2(bb.z), bc2(bb.w)};
#pragma unroll
            for (int i = 0; i < 4; i++)
#pragma unroll
                for (int j = 0; j < 4; j++) sp[i][j] = fma2(ap[i], bp[j], sp[i][j]);
        }
        float s[8][4];
#pragma unroll
        for (int i = 0; i < 4; i++)
#pragma unroll
            for (int j = 0; j < 4; j++) upk2(s[2 * i][j], s[2 * i + 1][j], sp[i][j]);

        float sc[8], psum[8];
#pragma unroll
        for (int i = 0; i < 8; i++) {
            float mx = fmaxf(fmaxf(s[i][0], s[i][1]), fmaxf(s[i][2], s[i][3]));
#pragma unroll
            for (int off = 8; off >= 1; off >>= 1)
                mx = fmaxf(mx, __shfl_xor_sync(0xffffffffu, mx, off));
            float nm = fmaxf(rm[i], mx);
            sc[i] = fast_exp(rm[i] - nm);
            rm[i] = nm;
            float ps = 0.0f;
#pragma unroll
            for (int j = 0; j < 4; j++) {
                s[i][j] = fast_exp(s[i][j] - nm);
                ps += s[i][j];
            }
#pragma unroll
            for (int off = 8; off >= 1; off >>= 1)
                ps += __shfl_xor_sync(0xffffffffu, ps, off);
            psum[i] = ps;
        }
        if (tx == 0) {
#pragma unroll
            for (int i = 0; i < 8; i++) {
                scale_s[ty8 + i] = sc[i];
                l_s[ty8 + i] = l_s[ty8 + i] * sc[i] + psum[i];
            }
        }
        __syncthreads();

        {
            ulonglong2 s0 = *(ulonglong2*)&scale_s[tx8];
            ulonglong2 s1 = *(ulonglong2*)&scale_s[tx8 + 4];
            ull srp[4] = {s0.x, s0.y, s1.x, s1.y};
#pragma unroll
            for (int r = 0; r < 4; r++)
#pragma unroll
                for (int u = 0; u < 8; u++) accp[r][u] = mul2(accp[r][u], srp[r]);
        }
#pragma unroll
        for (int j = 0; j < 4; j++) {
            float4 lo, hi;
            lo.x = s[0][j]; lo.y = s[1][j]; lo.z = s[2][j]; lo.w = s[3][j];
            hi.x = s[4][j]; hi.y = s[5][j]; hi.z = s[6][j]; hi.w = s[7][j];
            *(float4*)&P_s[(tx4 + j) * 132 + ty8] = lo;
            *(float4*)&P_s[(tx4 + j) * 132 + ty8 + 4] = hi;
        }
        __syncthreads();

#pragma unroll 4
        for (int m = 0; m < 64; m++) {
            ulonglong2 p0 = *(ulonglong2*)&P_s[m * 132 + tx8];
            ulonglong2 p1 = *(ulonglong2*)&P_s[m * 132 + tx8 + 4];
            ull pp[4] = {p0.x, p0.y, p1.x, p1.y};
            float4 g0 = *(float4*)&G_s[m * 128 + ty8];
            float4 g1 = *(float4*)&G_s[m * 128 + ty8 + 4];
            float gu[8] = {g0.x, g0.y, g0.z, g0.w, g1.x, g1.y, g1.z, g1.w};
#pragma unroll
            for (int u = 0; u < 8; u++) {
                ull gp = bc2(gu[u]);
#pragma unroll
                for (int r = 0; r < 4; r++) accp[r][u] = fma2(pp[r], gp, accp[r][u]);
            }
        }
    }

    __syncthreads();
    float inv[8];
    {
        float4 l0 = *(float4*)&l_s[tx8];
        float4 l1 = *(float4*)&l_s[tx8 + 4];
        inv[0] = 1.0f / l0.x; inv[1] = 1.0f / l0.y;
        inv[2] = 1.0f / l0.z; inv[3] = 1.0f / l0.w;
        inv[4] = 1.0f / l1.x; inv[5] = 1.0f / l1.y;
        inv[6] = 1.0f / l1.z; inv[7] = 1.0f / l1.w;
    }
    __syncthreads();

    float* yst = smf;
#pragma unroll
    for (int u = 0; u < 8; u++) {
        float a[8];
        upk2(a[0], a[1], accp[0][u]); upk2(a[2], a[3], accp[1][u]);
        upk2(a[4], a[5], accp[2][u]); upk2(a[6], a[7], accp[3][u]);
        float y0 = a[0] * inv[0], y1 = a[1] * inv[1];
        float y2 = a[2] * inv[2], y3 = a[3] * inv[3];
        float y4 = a[4] * inv[4], y5 = a[5] * inv[5];
        float y6 = a[6] * inv[6], y7 = a[7] * inv[7];
        float4 lo, hi;
        lo.x = y0; lo.y = y1; lo.z = y2; lo.w = y3;
        hi.x = y4; hi.y = y5; hi.z = y6; hi.w = y7;
        *(float4*)&yst[(ty8 + u) * 132 + tx8] = lo;
        *(float4*)&yst[(ty8 + u) * 132 + tx8 + 4] = hi;
        float p = ((y0 + y1) + (y2 + y3)) + ((y4 + y5) + (y6 + y7));
#pragma unroll
        for (int off = 8; off >= 1; off >>= 1)
            p += __shfl_xor_sync(0xffffffffu, p, off);
        if (tx == 0) atomicAdd(&d_mu[ty8 + u], p);
    }
    __syncthreads();

    float* yout = d_yT + (size_t)b * Gg * HW + n0;
    for (int f = tid; f < 128 * 32; f += 256) {
        int g = f >> 5, nq = (f & 31) * 4;
        *(float4*)(yout + (size_t)g * HW + nq) = *(float4*)&yst[g * 132 + nq];
    }
}

// ---------------- kernel 5: S = sum Y Y^T (syrk, FFMA2) ---------------------
__global__ __launch_bounds__(256, 2) void stats_kernel() {
    __shared__ float ys[32 * 132];
    const int b = blockIdx.x >> 4;
    const int nbase = (blockIdx.x & 15) * 256;
    const int tid = threadIdx.x;
    const int tx = tid & 15, ty = tid >> 4;

    ull Sap[8][4];
#pragma unroll
    for (int i = 0; i < 8; i++)
#pragma unroll
        for (int j = 0; j < 4; j++) Sap[i][j] = 0ULL;

    const float* yb = d_yT + (size_t)b * Gg * HW + nbase;
    for (int nc = 0; nc < 256; nc += 32) {
        for (int i = tid; i < 1024; i += 256) {
            int g = i >> 3, nq = (i & 7) * 4;
            float4 v = *(const float4*)(yb + (size_t)g * HW + nc + nq);
            ys[(nq + 0) * 132 + g] = v.x;
            ys[(nq + 1) * 132 + g] = v.y;
            ys[(nq + 2) * 132 + g] = v.z;
            ys[(nq + 3) * 132 + g] = v.w;
        }
        __syncthreads();
#pragma unroll 4
        for (int nn = 0; nn < 32; nn++) {
            float4 u0 = *(float4*)&ys[nn * 132 + ty * 8];
            float4 u1 = *(float4*)&ys[nn * 132 + ty * 8 + 4];
            ulonglong2 v0 = *(ulonglong2*)&ys[nn * 132 + tx * 8];
            ulonglong2 v1 = *(ulonglong2*)&ys[nn * 132 + tx * 8 + 4];
            ull vp[4] = {v0.x, v0.y, v1.x, v1.y};
            float ur[8] = {u0.x, u0.y, u0.z, u0.w, u1.x, u1.y, u1.z, u1.w};
#pragma unroll
            for (int i = 0; i < 8; i++) {
                ull up = bc2(ur[i]);
#pragma unroll
                for (int j = 0; j < 4; j++) Sap[i][j] = fma2(up, vp[j], Sap[i][j]);
            }
        }
        __syncthreads();
    }
#pragma unroll
    for (int i = 0; i < 8; i++)
#pragma unroll
        for (int j = 0; j < 4; j++) {
            float lo, hi;
            upk2(lo, hi, Sap[i][j]);
            atomicAdd(&d_S[(ty * 8 + i) * Gg + tx * 8 + 2 * j], lo);
            atomicAdd(&d_S[(ty * 8 + i) * Gg + tx * 8 + 2 * j + 1], hi);
        }
}

// ---------------- kernel 6: per-channel BN mean/rstd (analytic) -------------
__global__ void meanvar_kernel(const float* __restrict__ wz_w,
                               const float* __restrict__ wz_b) {
    const int c = blockIdx.x;
    const int g = threadIdx.x;
    __shared__ float wsh[Gg];
    __shared__ double red[Gg];
    wsh[g] = wz_w[(size_t)c * Gg + g];
    __syncthreads();
    double t = 0.0;
    for (int gp = 0; gp < Gg; gp++)
        t += (double)d_S[g * Gg + gp] * (double)wsh[gp];
    red[g] = t * (double)wsh[g];
    __syncthreads();
    for (int off = 64; off >= 1; off >>= 1) {
        if (g < off) red[g] += red[g + off];
        __syncthreads();
    }
    double wtsw = red[0];
    __syncthreads();
    red[g] = (double)wsh[g] * (double)d_mu[g];
    __syncthreads();
    for (int off = 64; off >= 1; off >>= 1) {
        if (g < off) red[g] += red[g + off];
        __syncthreads();
    }
    if (g == 0) {
        double wm = red[0];
        double inv = 1.0 / (double)(Bn * HW);
        double bz = (double)wz_b[c];
        double mean = wm * inv + bz;
        double e2 = wtsw * inv + 2.0 * bz * wm * inv + bz * bz;
        double var = e2 - mean * mean;
        d_meanC[c] = (float)mean;
        d_rstdC[c] = (float)rsqrt(var + 1e-5);
    }
}

// ---------------- kernel 7: wz GEMM + BN + residual via wmma tf32-split -----
__device__ __forceinline__ void g2_stage(
    float* sm, int buf, int k0, int c0, int n0, int tid,
    const float* wz_w, const float* yb)
{
    float* base = sm + buf * WBUF;
#pragma unroll
    for (int it = 0; it < 2; it++) {
        int f = tid + it * 256;
        int m = f >> 2, kq = (f & 3) * 4;
        float4 v = *(const float4*)(wz_w + (size_t)(c0 + m) * Gg + k0 + kq);
        w_split_store(base + m * 20 + kq, base + 2560 + m * 20 + kq, v);
    }
#pragma unroll
    for (int it = 0; it < 2; it++) {
        int f = tid + it * 256;
        int kk = f >> 5, nq = (f & 31) * 4;
        float4 v = *(const float4*)(yb + (size_t)(k0 + kk) * HW + n0 + nq);
        w_split_store(base + 5120 + kk * 132 + nq, base + 7232 + kk * 132 + nq, v);
    }
}

__global__ __launch_bounds__(256, 2) void gemm2_wmma_kernel(
    const float* __restrict__ x,
    const float* __restrict__ wz_w, const float* __restrict__ wz_b,
    const float* __restrict__ gamma, const float* __restrict__ beta,
    float* __restrict__ out)
{
    extern __shared__ float sm[];
    const int tid = threadIdx.x;
    const int w = tid >> 5;
    const int mbase = (w & 1) * 64;
    const int nbase = (w >> 1) * 32;
    const int b = blockIdx.z;
    const int c0 = blockIdx.y * 128;
    const int n0 = blockIdx.x * 128;
    const float* yb = d_yT + (size_t)b * Gg * HW;

    FragC acc[4][2];
#pragma unroll
    for (int i = 0; i < 4; i++)
#pragma unroll
        for (int j = 0; j < 2; j++) wmma::fill_fragment(acc[i][j], 0.0f);

    g2_stage(sm, 0, 0, c0, n0, tid, wz_w, yb);
    for (int c = 0; c < Gg / 16; c++) {
        __syncthreads();
        if (c + 1 < Gg / 16)
            g2_stage(sm, (c + 1) & 1, (c + 1) * 16, c0, n0, tid, wz_w, yb);
        w_mma_chunk(sm + (c & 1) * WBUF, mbase, nbase, acc);
    }

    __syncthreads();
    float* st = sm;
#pragma unroll
    for (int i = 0; i < 4; i++)
#pragma unroll
        for (int j = 0; j < 2; j++)
            wmma::store_matrix_sync(st + (mbase + i * 16) * 132 + nbase + j * 16,
                                    acc[i][j], 132, wmma::mem_row_major);
    __syncthreads();

#pragma unroll
    for (int it = 0; it < 16; it++) {
        int f = tid + it * 256;
        int row = f >> 5, nq = (f & 31) * 4;
        int c = c0 + row;
        float mn = d_meanC[c], rs = d_rstdC[c];
        float ga = gamma[c], be = beta[c], bz = wz_b[c];
        float a = rs * ga;
        float4 v = *(float4*)&st[row * 132 + nq];
        const float* xr = x + ((size_t)b * Cc + c) * HW + n0 + nq;
        float4 xv = *(const float4*)xr;
        float4 o;
        o.x = (v.x + bz - mn) * a + be + xv.x;
        o.y = (v.y + bz - mn) * a + be + xv.y;
        o.z = (v.z + bz - mn) * a + be + xv.z;
        o.w = (v.w + bz - mn) * a + be + xv.w;
        *(float4*)(out + ((size_t)b * Cc + c) * HW + n0 + nq) = o;
    }
}

// ---------------- launch -----------------------------------------------------
extern "C" void kernel_launch(void* const* d_in, const int* in_sizes, int n_in,
                              void* d_out, int out_size) {
    const float* x = (const float*)d_in[0];
    const float* g_w = (const float*)d_in[1];
    const float* g_b = (const float*)d_in[2];
    const float* th_w = (const float*)d_in[3];
    const float* th_b = (const float*)d_in[4];
    const float* ph_w = (const float*)d_in[5];
    const float* ph_b = (const float*)d_in[6];
    const float* wz_w = (const float*)d_in[7];
    const float* wz_b = (const float*)d_in[8];
    const float* gamma = (const float*)d_in[9];
    const float* beta = (const float*)d_in[10];
    float* out = (float*)d_out;

    const int wsmem = WSMEM_FLOATS * 4;
    (void)cudaFuncSetAttribute(attn_kernel,
                               cudaFuncAttributeMaxDynamicSharedMemorySize,
                               ATT_SMEM_FLOATS * 4);
    (void)cudaFuncSetAttribute(gemm1_wmma_kernel,
                               cudaFuncAttributeMaxDynamicSharedMemorySize, wsmem);
    (void)cudaFuncSetAttribute(gemm2_wmma_kernel,
                               cudaFuncAttributeMaxDynamicSharedMemorySize, wsmem);

    zero_kernel<<<64, 256>>>();
    gemm1_wmma_kernel<<<dim3(HW / 128, 2, Bn), 256, wsmem>>>(
        x, g_w, g_b, th_w, th_b, ph_w, ph_b);
    pool_kernel<<<(Bn * 192 * Mm + 255) / 256, 256>>>();
    attn_kernel<<<dim3(HW / 128, Bn), 256, ATT_SMEM_FLOATS * 4>>>();
    stats_kernel<<<128, 256>>>();
    meanvar_kernel<<<Cc, Gg>>>(wz_w, wz_b);
    gemm2_wmma_kernel<<<dim3(HW / 128, Cc / 128, Bn), 256, wsmem>>>(
        x, wz_w, wz_b, gamma, beta, out);
}

// round 9
// speedup vs baseline: 1.2706x; 1.2706x over previous
#include <cuda_runtime.h>
#include <math.h>

#define Bn 8
#define Cc 512
#define HW 4096
#define Mm 1024
#define Dd 64
#define Gg 128

typedef unsigned long long ull;

// ---------------- packed f32x2 primitives (Blackwell) ----------------------
__device__ __forceinline__ ull pk2(float lo, float hi) {
    ull r;
    asm("mov.b64 %0, {%1, %2};" : "=l"(r) : "f"(lo), "f"(hi));
    return r;
}
__device__ __forceinline__ ull bc2(float v) { return pk2(v, v); }
__device__ __forceinline__ ull fma2(ull a, ull b, ull c) {
    ull d;
    asm("fma.rn.f32x2 %0, %1, %2, %3;" : "=l"(d) : "l"(a), "l"(b), "l"(c));
    return d;
}
__device__ __forceinline__ ull mul2(ull a, ull b) {
    ull d;
    asm("mul.rn.f32x2 %0, %1, %2;" : "=l"(d) : "l"(a), "l"(b));
    return d;
}
__device__ __forceinline__ void upk2(float& lo, float& hi, ull v) {
    asm("mov.b64 {%0, %1}, %2;" : "=f"(lo), "=f"(hi) : "l"(v));
}

// ---------------- scratch ---------------------------------------------------
__device__ float d_tpg[Bn * 256 * HW];   // only theta rows (0..63) written now
__device__ float d_phiP[Bn * Dd * Mm];
__device__ float d_gPT[Bn * Mm * Gg];    // pooled g, transposed [b][m][g]
__device__ float d_yT[Bn * Gg * HW];
__device__ float d_S[Gg * Gg];
__device__ float d_mu[Gg];
__device__ float d_meanC[Cc];
__device__ float d_rstdC[Cc];

// ---------------- fast exp on the FMA pipe ----------------------------------
__device__ __forceinline__ float fast_exp(float x) {
    x = fmaxf(x, -87.0f);
    float t = fmaf(x, 1.4426950408889634f, 12582912.0f);
    float n = t - 12582912.0f;
    int e = __float_as_int(t) - 0x4B400000;
    float r = fmaf(n, -6.93145752e-1f, x);
    r = fmaf(n, -1.42860677e-6f, r);
    float p = 1.3888889e-3f;
    p = fmaf(p, r, 8.3333333e-3f);
    p = fmaf(p, r, 4.1666668e-2f);
    p = fmaf(p, r, 1.6666667e-1f);
    p = fmaf(p, r, 5.0e-1f);
    p = fmaf(p, r, 1.0f);
    p = fmaf(p, r, 1.0f);
    return __int_as_float(__float_as_int(p) + (e << 23));
}

// ---------------- kernel 0: zero S, mu --------------------------------------
__global__ void zero_kernel() {
    int i = blockIdx.x * 256 + threadIdx.x;
    if (i < Gg * Gg) d_S[i] = 0.0f;
    if (i < Gg) d_mu[i] = 0.0f;
}

// ---------------- kernel 1: conv1x1 (theta|phi|g), FFMA2, fused maxpool -----
// grid (32, 2, 8): y=0 -> rows 0..127 (theta 0-63 direct, phi 64-127 pooled),
//                  y=1 -> rows 128..255 (g, pooled+transposed).
// dynamic smem: main loop uses As[16*128]|Bs[16*128]; epilogue reuses as
// st[64][132] staging for pooling. 8448 floats = 33792 B.
#define G1_SMEM_FLOATS 8448
__global__ __launch_bounds__(256, 2) void gemm1_kernel(
    const float* __restrict__ x,
    const float* __restrict__ g_w, const float* __restrict__ g_b,
    const float* __restrict__ th_w, const float* __restrict__ th_b,
    const float* __restrict__ ph_w, const float* __restrict__ ph_b)
{
    extern __shared__ float smg[];
    float* As = smg;            // [16][128]
    float* Bs = smg + 2048;     // [16][128]

    const int b = blockIdx.z;
    const int row0g = blockIdx.y * 128;
    const int n0 = blockIdx.x * 128;
    const int tid = threadIdx.x;
    const int tx = tid & 15, ty = tid >> 4;
    const float* xb = x + (size_t)b * Cc * HW;

    ull accp[8][4];
#pragma unroll
    for (int i = 0; i < 8; i++)
#pragma unroll
        for (int j = 0; j < 4; j++) accp[i][j] = 0ULL;

    const int am = tid >> 1;
    const int akq = (tid & 1) * 8;
    const float* wrow;
    {
        int o = row0g + am;
        if (o < 64) wrow = th_w + (size_t)o * Cc;
        else if (o < 128) wrow = ph_w + (size_t)(o - 64) * Cc;
        else wrow = g_w + (size_t)(o - 128) * Cc;
    }
    const int bkk = tid >> 4;
    const int bnq = (tid & 15) * 8;

    float4 wa = *(const float4*)(wrow + akq);
    float4 wb = *(const float4*)(wrow + akq + 4);
    const float* src0 = xb + (size_t)bkk * HW + n0 + bnq;
    float4 v0 = *(const float4*)src0;
    float4 v1 = *(const float4*)(src0 + 4);

    for (int k0 = 0; k0 < Cc; k0 += 16) {
        As[(akq + 0) * 128 + am] = wa.x; As[(akq + 1) * 128 + am] = wa.y;
        As[(akq + 2) * 128 + am] = wa.z; As[(akq + 3) * 128 + am] = wa.w;
        As[(akq + 4) * 128 + am] = wb.x; As[(akq + 5) * 128 + am] = wb.y;
        As[(akq + 6) * 128 + am] = wb.z; As[(akq + 7) * 128 + am] = wb.w;
        *(float4*)&Bs[bkk * 128 + bnq] = v0;
        *(float4*)&Bs[bkk * 128 + bnq + 4] = v1;
        __syncthreads();

        if (k0 + 16 < Cc) {
            wa = *(const float4*)(wrow + k0 + 16 + akq);
            wb = *(const float4*)(wrow + k0 + 16 + akq + 4);
            const float* src = xb + (size_t)(k0 + 16 + bkk) * HW + n0 + bnq;
            v0 = *(const float4*)src;
            v1 = *(const float4*)(src + 4);
        }

#pragma unroll
        for (int kk = 0; kk < 16; kk++) {
            float4 a0 = *(float4*)&As[kk * 128 + ty * 8];
            float4 a1 = *(float4*)&As[kk * 128 + ty * 8 + 4];
            ulonglong2 q0 = *(ulonglong2*)&Bs[kk * 128 + tx * 8];
            ulonglong2 q1 = *(ulonglong2*)&Bs[kk * 128 + tx * 8 + 4];
            ull bp[4] = {q0.x, q0.y, q1.x, q1.y};
            float ar[8] = {a0.x, a0.y, a0.z, a0.w, a1.x, a1.y, a1.z, a1.w};
#pragma unroll
            for (int i = 0; i < 8; i++) {
                ull ap = bc2(ar[i]);
#pragma unroll
                for (int j = 0; j < 4; j++) accp[i][j] = fma2(ap, bp[j], accp[i][j]);
            }
        }
        __syncthreads();
    }

    // ---- epilogue: unpack; theta stored direct, phi/g staged+pooled ----
    float av[8][8];
#pragma unroll
    for (int i = 0; i < 8; i++) {
        upk2(av[i][0], av[i][1], accp[i][0]);
        upk2(av[i][2], av[i][3], accp[i][1]);
        upk2(av[i][4], av[i][5], accp[i][2]);
        upk2(av[i][6], av[i][7], accp[i][3]);
    }
    float* st = smg;   // [64][132]

    if (row0g == 0) {
        if (ty < 8) {
            // theta rows 0..63: direct global store
#pragma unroll
            for (int i = 0; i < 8; i++) {
                int o = ty * 8 + i;
                float bv = th_b[o];
                float* orow = d_tpg + ((size_t)b * 256 + o) * HW + n0 + tx * 8;
                float4 o0, o1;
                o0.x = av[i][0] + bv; o0.y = av[i][1] + bv;
                o0.z = av[i][2] + bv; o0.w = av[i][3] + bv;
                o1.x = av[i][4] + bv; o1.y = av[i][5] + bv;
                o1.z = av[i][6] + bv; o1.w = av[i][7] + bv;
                *(float4*)orow = o0;
                *(float4*)(orow + 4) = o1;
            }
        } else {
            // phi rows 64..127: stage st[row-64][n]
#pragma unroll
            for (int i = 0; i < 8; i++) {
                int o = ty * 8 + i;             // 64..127
                float bv = ph_b[o - 64];
                int rr = o - 64;
                float4 o0, o1;
                o0.x = av[i][0] + bv; o0.y = av[i][1] + bv;
                o0.z = av[i][2] + bv; o0.w = av[i][3] + bv;
                o1.x = av[i][4] + bv; o1.y = av[i][5] + bv;
                o1.z = av[i][6] + bv; o1.w = av[i][7] + bv;
                *(float4*)&st[rr * 132 + tx * 8] = o0;
                *(float4*)&st[rr * 132 + tx * 8 + 4] = o1;
            }
        }
        __syncthreads();
        // pool phi: out [c][pm], pm = blockIdx.x*32 + pw
        for (int t = tid; t < 2048; t += 256) {
            int rr = t >> 5, pw = t & 31;
            const float* sp = &st[rr * 132 + 2 * pw];
            float v = fmaxf(fmaxf(sp[0], sp[1]), fmaxf(sp[64], sp[65]));
            d_phiP[((size_t)b * Dd + rr) * Mm + blockIdx.x * 32 + pw] = v;
        }
    } else {
        // g rows 128..255 -> channels 0..127, two passes of 64 rows
#pragma unroll
        for (int pass = 0; pass < 2; pass++) {
            if ((ty >> 3) == pass) {
#pragma unroll
                for (int i = 0; i < 8; i++) {
                    int gch = ty * 8 + i;        // 0..127
                    float bv = g_b[gch];
                    int rr = gch - pass * 64;    // 0..63
                    float4 o0, o1;
                    o0.x = av[i][0] + bv; o0.y = av[i][1] + bv;
                    o0.z = av[i][2] + bv; o0.w = av[i][3] + bv;
                    o1.x = av[i][4] + bv; o1.y = av[i][5] + bv;
                    o1.z = av[i][6] + bv; o1.w = av[i][7] + bv;
                    *(float4*)&st[rr * 132 + tx * 8] = o0;
                    *(float4*)&st[rr * 132 + tx * 8 + 4] = o1;
                }
            }
            __syncthreads();
            // pool g: out [pm][gch] (transposed layout) — rr fastest for coalescing
            for (int t = tid; t < 2048; t += 256) {
                int rr = t & 63, pw = t >> 6;
                const float* sp = &st[rr * 132 + 2 * pw];
                float v = fmaxf(fmaxf(sp[0], sp[1]), fmaxf(sp[64], sp[65]));
                int gch = pass * 64 + rr;
                d_gPT[((size_t)b * Mm + blockIdx.x * 32 + pw) * Gg + gch] = v;
            }
            __syncthreads();
        }
    }
}

// ---------------- kernel 3: fused attention, FFMA2, 2 CTAs/SM ---------------
#define ATT_SMEM_FLOATS (8192 + 8448 + 8192 + 128 + 128)
__global__ __launch_bounds__(256, 2) void attn_kernel() {
    extern __shared__ float smf[];
    float* th_s = smf;                    // [c][n] stride 128
    float* phi_s = smf + 8192;            // [c][m] stride 64 (aliases P)
    float* P_s = smf + 8192;              // [m][n] stride 132
    float* G_s = smf + 16640;             // [m][g] stride 128
    float* scale_s = smf + 24832;         // [128]
    float* l_s = smf + 24960;             // [128]

    const int b = blockIdx.y;
    const int n0 = blockIdx.x * 128;
    const int tid = threadIdx.x;
    const int tx = tid & 15, ty = tid >> 4;
    const int ty8 = ty * 8, tx4 = tx * 4, tx8 = tx * 8;

    const float* thg = d_tpg + (size_t)b * 256 * HW + n0;
    for (int f = tid; f < 64 * 32; f += 256) {
        int c = f >> 5, nq = (f & 31) * 4;
        *(float4*)&th_s[c * 128 + nq] = *(const float4*)(thg + (size_t)c * HW + nq);
    }
    if (tid < 128) l_s[tid] = 0.0f;

    float rm[8];
    ull accp[4][8];
#pragma unroll
    for (int i = 0; i < 8; i++) rm[i] = -1e30f;
#pragma unroll
    for (int r = 0; r < 4; r++)
#pragma unroll
        for (int u = 0; u < 8; u++) accp[r][u] = 0ULL;

    const float* phig = d_phiP + (size_t)b * Dd * Mm;
    const float* gTg = d_gPT + (size_t)b * Mm * Gg;

    for (int m0 = 0; m0 < Mm; m0 += 64) {
        __syncthreads();
        for (int f = tid; f < 64 * 16; f += 256) {
            int c = f >> 4, mq = (f & 15) * 4;
            *(float4*)&phi_s[c * 64 + mq] = *(const float4*)(phig + (size_t)c * Mm + m0 + mq);
        }
        for (int f = tid; f < 64 * 32; f += 256) {
            int m = f >> 5, gq = (f & 31) * 4;
            *(float4*)&G_s[m * 128 + gq] = *(const float4*)(gTg + (size_t)(m0 + m) * Gg + gq);
        }
        __syncthreads();

        ull sp[4][4];
#pragma unroll
        for (int i = 0; i < 4; i++)
#pragma unroll
            for (int j = 0; j < 4; j++) sp[i][j] = 0ULL;
#pragma unroll 8
        for (int c = 0; c < 64; c++) {
            ulonglong2 t0 = *(ulonglong2*)&th_s[c * 128 + ty8];
            ulonglong2 t1 = *(ulonglong2*)&th_s[c * 128 + ty8 + 4];
            ull ap[4] = {t0.x, t0.y, t1.x, t1.y};
            float4 bb = *(float4*)&phi_s[c * 64 + tx4];
            ull bp[4] = {bc2(bb.x), bc2(bb.y), bc2(bb.z), bc2(bb.w)};
#pragma unroll
            for (int i = 0; i < 4; i++)
#pragma unroll
                for (int j = 0; j < 4; j++) sp[i][j] = fma2(ap[i], bp[j], sp[i][j]);
        }
        float s[8][4];
#pragma unroll
        for (int i = 0; i < 4; i++)
#pragma unroll
            for (int j = 0; j < 4; j++) upk2(s[2 * i][j], s[2 * i + 1][j], sp[i][j]);

        float sc[8], psum[8];
#pragma unroll
        for (int i = 0; i < 8; i++) {
            float mx = fmaxf(fmaxf(s[i][0], s[i][1]), fmaxf(s[i][2], s[i][3]));
#pragma unroll
            for (int off = 8; off >= 1; off >>= 1)
                mx = fmaxf(mx, __shfl_xor_sync(0xffffffffu, mx, off));
            float nm = fmaxf(rm[i], mx);
            sc[i] = fast_exp(rm[i] - nm);
            rm[i] = nm;
            float ps = 0.0f;
#pragma unroll
            for (int j = 0; j < 4; j++) {
                s[i][j] = fast_exp(s[i][j] - nm);
                ps += s[i][j];
            }
#pragma unroll
            for (int off = 8; off >= 1; off >>= 1)
                ps += __shfl_xor_sync(0xffffffffu, ps, off);
            psum[i] = ps;
        }
        if (tx == 0) {
#pragma unroll
            for (int i = 0; i < 8; i++) {
                scale_s[ty8 + i] = sc[i];
                l_s[ty8 + i] = l_s[ty8 + i] * sc[i] + psum[i];
            }
        }
        __syncthreads();

        {
            ulonglong2 s0 = *(ulonglong2*)&scale_s[tx8];
            ulonglong2 s1 = *(ulonglong2*)&scale_s[tx8 + 4];
            ull srp[4] = {s0.x, s0.y, s1.x, s1.y};
#pragma unroll
            for (int r = 0; r < 4; r++)
#pragma unroll
                for (int u = 0; u < 8; u++) accp[r][u] = mul2(accp[r][u], srp[r]);
        }
#pragma unroll
        for (int j = 0; j < 4; j++) {
            float4 lo, hi;
            lo.x = s[0][j]; lo.y = s[1][j]; lo.z = s[2][j]; lo.w = s[3][j];
            hi.x = s[4][j]; hi.y = s[5][j]; hi.z = s[6][j]; hi.w = s[7][j];
            *(float4*)&P_s[(tx4 + j) * 132 + ty8] = lo;
            *(float4*)&P_s[(tx4 + j) * 132 + ty8 + 4] = hi;
        }
        __syncthreads();

#pragma unroll 4
        for (int m = 0; m < 64; m++) {
            ulonglong2 p0 = *(ulonglong2*)&P_s[m * 132 + tx8];
            ulonglong2 p1 = *(ulonglong2*)&P_s[m * 132 + tx8 + 4];
            ull pp[4] = {p0.x, p0.y, p1.x, p1.y};
            float4 g0 = *(float4*)&G_s[m * 128 + ty8];
            float4 g1 = *(float4*)&G_s[m * 128 + ty8 + 4];
            float gu[8] = {g0.x, g0.y, g0.z, g0.w, g1.x, g1.y, g1.z, g1.w};
#pragma unroll
            for (int u = 0; u < 8; u++) {
                ull gp = bc2(gu[u]);
#pragma unroll
                for (int r = 0; r < 4; r++) accp[r][u] = fma2(pp[r], gp, accp[r][u]);
            }
        }
    }

    __syncthreads();
    float inv[8];
    {
        float4 l0 = *(float4*)&l_s[tx8];
        float4 l1 = *(float4*)&l_s[tx8 + 4];
        inv[0] = 1.0f / l0.x; inv[1] = 1.0f / l0.y;
        inv[2] = 1.0f / l0.z; inv[3] = 1.0f / l0.w;
        inv[4] = 1.0f / l1.x; inv[5] = 1.0f / l1.y;
        inv[6] = 1.0f / l1.z; inv[7] = 1.0f / l1.w;
    }
    __syncthreads();

    float* yst = smf;
#pragma unroll
    for (int u = 0; u < 8; u++) {
        float a[8];
        upk2(a[0], a[1], accp[0][u]); upk2(a[2], a[3], accp[1][u]);
        upk2(a[4], a[5], accp[2][u]); upk2(a[6], a[7], accp[3][u]);
        float y0 = a[0] * inv[0], y1 = a[1] * inv[1];
        float y2 = a[2] * inv[2], y3 = a[3] * inv[3];
        float y4 = a[4] * inv[4], y5 = a[5] * inv[5];
        float y6 = a[6] * inv[6], y7 = a[7] * inv[7];
        float4 lo, hi;
        lo.x = y0; lo.y = y1; lo.z = y2; lo.w = y3;
        hi.x = y4; hi.y = y5; hi.z = y6; hi.w = y7;
        *(float4*)&yst[(ty8 + u) * 132 + tx8] = lo;
        *(float4*)&yst[(ty8 + u) * 132 + tx8 + 4] = hi;
        float p = ((y0 + y1) + (y2 + y3)) + ((y4 + y5) + (y6 + y7));
#pragma unroll
        for (int off = 8; off >= 1; off >>= 1)
            p += __shfl_xor_sync(0xffffffffu, p, off);
        if (tx == 0) atomicAdd(&d_mu[ty8 + u], p);
    }
    __syncthreads();

    float* yout = d_yT + (size_t)b * Gg * HW + n0;
    for (int f = tid; f < 128 * 32; f += 256) {
        int g = f >> 5, nq = (f & 31) * 4;
        *(float4*)(yout + (size_t)g * HW + nq) = *(float4*)&yst[g * 132 + nq];
    }
}

// ---------------- kernel 5: S = sum Y Y^T (syrk, FFMA2) ---------------------
__global__ __launch_bounds__(256, 2) void stats_kernel() {
    __shared__ float ys[32 * 132];
    const int b = blockIdx.x >> 4;
    const int nbase = (blockIdx.x & 15) * 256;
    const int tid = threadIdx.x;
    const int tx = tid & 15, ty = tid >> 4;

    ull Sap[8][4];
#pragma unroll
    for (int i = 0; i < 8; i++)
#pragma unroll
        for (int j = 0; j < 4; j++) Sap[i][j] = 0ULL;

    const float* yb = d_yT + (size_t)b * Gg * HW + nbase;
    for (int nc = 0; nc < 256; nc += 32) {
        for (int i = tid; i < 1024; i += 256) {
            int g = i >> 3, nq = (i & 7) * 4;
            float4 v = *(const float4*)(yb + (size_t)g * HW + nc + nq);
            ys[(nq + 0) * 132 + g] = v.x;
            ys[(nq + 1) * 132 + g] = v.y;
            ys[(nq + 2) * 132 + g] = v.z;
            ys[(nq + 3) * 132 + g] = v.w;
        }
        __syncthreads();
#pragma unroll 4
        for (int nn = 0; nn < 32; nn++) {
            float4 u0 = *(float4*)&ys[nn * 132 + ty * 8];
            float4 u1 = *(float4*)&ys[nn * 132 + ty * 8 + 4];
            ulonglong2 v0 = *(ulonglong2*)&ys[nn * 132 + tx * 8];
            ulonglong2 v1 = *(ulonglong2*)&ys[nn * 132 + tx * 8 + 4];
            ull vp[4] = {v0.x, v0.y, v1.x, v1.y};
            float ur[8] = {u0.x, u0.y, u0.z, u0.w, u1.x, u1.y, u1.z, u1.w};
#pragma unroll
            for (int i = 0; i < 8; i++) {
                ull up = bc2(ur[i]);
#pragma unroll
                for (int j = 0; j < 4; j++) Sap[i][j] = fma2(up, vp[j], Sap[i][j]);
            }
        }
        __syncthreads();
    }
#pragma unroll
    for (int i = 0; i < 8; i++)
#pragma unroll
        for (int j = 0; j < 4; j++) {
            float lo, hi;
            upk2(lo, hi, Sap[i][j]);
            atomicAdd(&d_S[(ty * 8 + i) * Gg + tx * 8 + 2 * j], lo);
            atomicAdd(&d_S[(ty * 8 + i) * Gg + tx * 8 + 2 * j + 1], hi);
        }
}

// ---------------- kernel 6: per-channel BN mean/rstd (analytic) -------------
__global__ void meanvar_kernel(const float* __restrict__ wz_w,
                               const float* __restrict__ wz_b) {
    const int c = blockIdx.x;
    const int g = threadIdx.x;
    __shared__ float wsh[Gg];
    __shared__ double red[Gg];
    wsh[g] = wz_w[(size_t)c * Gg + g];
    __syncthreads();
    double t = 0.0;
    for (int gp = 0; gp < Gg; gp++)
        t += (double)d_S[g * Gg + gp] * (double)wsh[gp];
    red[g] = t * (double)wsh[g];
    __syncthreads();
    for (int off = 64; off >= 1; off >>= 1) {
        if (g < off) red[g] += red[g + off];
        __syncthreads();
    }
    double wtsw = red[0];
    __syncthreads();
    red[g] = (double)wsh[g] * (double)d_mu[g];
    __syncthreads();
    for (int off = 64; off >= 1; off >>= 1) {
        if (g < off) red[g] += red[g + off];
        __syncthreads();
    }
    if (g == 0) {
        double wm = red[0];
        double inv = 1.0 / (double)(Bn * HW);
        double bz = (double)wz_b[c];
        double mean = wm * inv + bz;
        double e2 = wtsw * inv + 2.0 * bz * wm * inv + bz * bz;
        double var = e2 - mean * mean;
        d_meanC[c] = (float)mean;
        d_rstdC[c] = (float)rsqrt(var + 1e-5);
    }
}

// ---------------- kernel 7: wz GEMM + BN + residual, FFMA2 ------------------
__global__ __launch_bounds__(256, 2) void gemm2_kernel(
    const float* __restrict__ x,
    const float* __restrict__ wz_w, const float* __restrict__ wz_b,
    const float* __restrict__ gamma, const float* __restrict__ beta,
    float* __restrict__ out)
{
    __shared__ float As[16][128];
    __shared__ float Bs[16][128];
    const int b = blockIdx.z;
    const int c0 = blockIdx.y * 128;
    const int n0 = blockIdx.x * 128;
    const int tid = threadIdx.x;
    const int tx = tid & 15, ty = tid >> 4;

    ull accp[8][4];
#pragma unroll
    for (int i = 0; i < 8; i++)
#pragma unroll
        for (int j = 0; j < 4; j++) accp[i][j] = 0ULL;

    const int am = tid >> 1;
    const int akq = (tid & 1) * 8;
    const float* wrow = wz_w + (size_t)(c0 + am) * Gg;
    const int bkk = tid >> 4;
    const int bnq = (tid & 15) * 8;
    const float* yb = d_yT + (size_t)b * Gg * HW;

    float4 wa = *(const float4*)(wrow + akq);
    float4 wb = *(const float4*)(wrow + akq + 4);
    const float* src0 = yb + (size_t)bkk * HW + n0 + bnq;
    float4 v0 = *(const float4*)src0;
    float4 v1 = *(const float4*)(src0 + 4);

    for (int k0 = 0; k0 < Gg; k0 += 16) {
        As[akq + 0][am] = wa.x; As[akq + 1][am] = wa.y;
        As[akq + 2][am] = wa.z; As[akq + 3][am] = wa.w;
        As[akq + 4][am] = wb.x; As[akq + 5][am] = wb.y;
        As[akq + 6][am] = wb.z; As[akq + 7][am] = wb.w;
        *(float4*)&Bs[bkk][bnq] = v0;
        *(float4*)&Bs[bkk][bnq + 4] = v1;
        __syncthreads();

        if (k0 + 16 < Gg) {
            wa = *(const float4*)(wrow + k0 + 16 + akq);
            wb = *(const float4*)(wrow + k0 + 16 + akq + 4);
            const float* src = yb + (size_t)(k0 + 16 + bkk) * HW + n0 + bnq;
            v0 = *(const float4*)src;
            v1 = *(const float4*)(src + 4);
        }

#pragma unroll
        for (int kk = 0; kk < 16; kk++) {
            float4 a0 = *(float4*)&As[kk][ty * 8];
            float4 a1 = *(float4*)&As[kk][ty * 8 + 4];
            ulonglong2 q0 = *(ulonglong2*)&Bs[kk][tx * 8];
            ulonglong2 q1 = *(ulonglong2*)&Bs[kk][tx * 8 + 4];
            ull bp[4] = {q0.x, q0.y, q1.x, q1.y};
            float ar[8] = {a0.x, a0.y, a0.z, a0.w, a1.x, a1.y, a1.z, a1.w};
#pragma unroll
            for (int i = 0; i < 8; i++) {
                ull ap = bc2(ar[i]);
#pragma unroll
                for (int j = 0; j < 4; j++) accp[i][j] = fma2(ap, bp[j], accp[i][j]);
            }
        }
        __syncthreads();
    }

#pragma unroll
    for (int i = 0; i < 8; i++) {
        int c = c0 + ty * 8 + i;
        float mn = d_meanC[c], rs = d_rstdC[c];
        float ga = gamma[c], be = beta[c], bz = wz_b[c];
        float a = rs * ga;
        float av[8];
        upk2(av[0], av[1], accp[i][0]); upk2(av[2], av[3], accp[i][1]);
        upk2(av[4], av[5], accp[i][2]); upk2(av[6], av[7], accp[i][3]);
        const float* xr = x + ((size_t)b * Cc + c) * HW + n0 + tx * 8;
        float* orow = out + ((size_t)b * Cc + c) * HW + n0 + tx * 8;
        float4 x0 = *(const float4*)xr;
        float4 x1 = *(const float4*)(xr + 4);
        float4 o0, o1;
        o0.x = (av[0] + bz - mn) * a + be + x0.x;
        o0.y = (av[1] + bz - mn) * a + be + x0.y;
        o0.z = (av[2] + bz - mn) * a + be + x0.z;
        o0.w = (av[3] + bz - mn) * a + be + x0.w;
        o1.x = (av[4] + bz - mn) * a + be + x1.x;
        o1.y = (av[5] + bz - mn) * a + be + x1.y;
        o1.z = (av[6] + bz - mn) * a + be + x1.z;
        o1.w = (av[7] + bz - mn) * a + be + x1.w;
        *(float4*)orow = o0;
        *(float4*)(orow + 4) = o1;
    }
}

// ---------------- launch -----------------------------------------------------
extern "C" void kernel_launch(void* const* d_in, const int* in_sizes, int n_in,
                              void* d_out, int out_size) {
    const float* x = (const float*)d_in[0];
    const float* g_w = (const float*)d_in[1];
    const float* g_b = (const float*)d_in[2];
    const float* th_w = (const float*)d_in[3];
    const float* th_b = (const float*)d_in[4];
    const float* ph_w = (const float*)d_in[5];
    const float* ph_b = (const float*)d_in[6];
    const float* wz_w = (const float*)d_in[7];
    const float* wz_b = (const float*)d_in[8];
    const float* gamma = (const float*)d_in[9];
    const float* beta = (const float*)d_in[10];
    float* out = (float*)d_out;

    (void)cudaFuncSetAttribute(attn_kernel,
                               cudaFuncAttributeMaxDynamicSharedMemorySize,
                               ATT_SMEM_FLOATS * 4);

    zero_kernel<<<64, 256>>>();
    gemm1_kernel<<<dim3(HW / 128, 2, Bn), 256, G1_SMEM_FLOATS * 4>>>(
        x, g_w, g_b, th_w, th_b, ph_w, ph_b);
    attn_kernel<<<dim3(HW / 128, Bn), 256, ATT_SMEM_FLOATS * 4>>>();
    stats_kernel<<<128, 256>>>();
    meanvar_kernel<<<Cc, Gg>>>(wz_w, wz_b);
    gemm2_kernel<<<dim3(HW / 128, Cc / 128, Bn), 256>>>(x, wz_w, wz_b, gamma, beta, out);
}